// round 2
// baseline (speedup 1.0000x reference)
#include <cuda_runtime.h>
#include <cstdint>
#include <cfloat>
#include <math.h>

#define VOC   10000
#define EMB   512
#define HID   1024
#define BATCH 128
#define SEQT  64
#define STEPS 63
#define CTXW  4096
#define G4H   4096
#define NBLK  128
#define NTHR  256
#define NTILE_OUT 313   // ceil(10000/32)

// ------------- persistent device scratch (static: no allocation) -------------
__device__ float g_hn[BATCH * G4H];          // h_n @ W_ih1[:,E:].T + b_ih1 + b_hh1
__device__ float g_x[BATCH * EMB];           // current input embedding
__device__ float g_h1[2][BATCH * HID];       // ping-pong hidden layer 1
__device__ float g_h2[2][BATCH * HID];       // ping-pong hidden layer 2
__device__ float g_pmax[BATCH][NTILE_OUT];   // per-tile argmax partials
__device__ int   g_pidx[BATCH][NTILE_OUT];
__device__ unsigned g_count;                 // barrier arrive counter
__device__ unsigned g_gen;                   // barrier generation

__device__ __forceinline__ float sigmf(float x) { return 1.0f / (1.0f + expf(-x)); }

// ------------- grid-wide sense barrier (all NBLK blocks co-resident) ---------
__device__ __forceinline__ void gbar() {
    __syncthreads();
    if (threadIdx.x == 0) {
        __threadfence();
        unsigned gen = *((volatile unsigned*)&g_gen);
        unsigned arrived = atomicAdd(&g_count, 1);
        if (arrived == NBLK - 1) {
            atomicExch(&g_count, 0);
            __threadfence();
            atomicAdd(&g_gen, 1);
        } else {
            while (*((volatile unsigned*)&g_gen) == gen) __nanosleep(64);
        }
        __threadfence();
    }
    __syncthreads();
}

// ------------- tiled fp32 GEMM accumulate -----------------------------------
// C tile: 128 rows x 32 "columns". Thread (rg,jj): rows rg*4..rg*4+3, cols
// {g*8+jj : g=0..3}. GATED: global W row = g*HID + j0 + jj (gate-grouped so
// the LSTM cell update fuses without an extra barrier). Else: row = j0 + wr.
template<bool GATED>
__device__ __forceinline__ void mm_accum(float acc[4][4],
    const float* __restrict__ A, int lda, int K,
    const float* __restrict__ W, int ldw, int wk0,
    int j0, int growmax,
    float (* __restrict__ sA)[17], float (* __restrict__ sW)[17])
{
    const int tid = threadIdx.x;
    const int rg  = tid >> 3;
    const int jj  = tid & 7;
    const int lr  = tid >> 1;          // A loader: row
    const int lkh = (tid & 1) << 3;    // A loader: k-half (0 or 8)
    const int wr  = tid >> 3;          // W loader: smem row 0..31
    const int wk  = (tid & 7) << 1;    // W loader: k pair
    int grow = GATED ? (((wr >> 3) * HID) + j0 + (wr & 7)) : (j0 + wr);
    if (!GATED && grow > growmax) grow = growmax;
    const float* wp = W + (size_t)grow * ldw + wk0 + wk;
    const float* ap = A + (size_t)lr * lda + lkh;

    for (int k0 = 0; k0 < K; k0 += 16) {
        __syncthreads();
        float4 v0 = __ldcg((const float4*)(ap + k0));
        float4 v1 = __ldcg((const float4*)(ap + k0) + 1);
        float2 wv = *(const float2*)(wp + k0);
        float* sp = &sA[lr][lkh];
        sp[0]=v0.x; sp[1]=v0.y; sp[2]=v0.z; sp[3]=v0.w;
        sp[4]=v1.x; sp[5]=v1.y; sp[6]=v1.z; sp[7]=v1.w;
        sW[wr][wk] = wv.x; sW[wr][wk + 1] = wv.y;
        __syncthreads();
        #pragma unroll
        for (int k = 0; k < 16; k++) {
            float a0 = sA[rg*4+0][k];
            float a1 = sA[rg*4+1][k];
            float a2 = sA[rg*4+2][k];
            float a3 = sA[rg*4+3][k];
            float w0 = sW[jj][k];
            float w1 = sW[8 + jj][k];
            float w2 = sW[16 + jj][k];
            float w3 = sW[24 + jj][k];
            acc[0][0] = fmaf(a0,w0,acc[0][0]); acc[0][1] = fmaf(a0,w1,acc[0][1]);
            acc[0][2] = fmaf(a0,w2,acc[0][2]); acc[0][3] = fmaf(a0,w3,acc[0][3]);
            acc[1][0] = fmaf(a1,w0,acc[1][0]); acc[1][1] = fmaf(a1,w1,acc[1][1]);
            acc[1][2] = fmaf(a1,w2,acc[1][2]); acc[1][3] = fmaf(a1,w3,acc[1][3]);
            acc[2][0] = fmaf(a2,w0,acc[2][0]); acc[2][1] = fmaf(a2,w1,acc[2][1]);
            acc[2][2] = fmaf(a2,w2,acc[2][2]); acc[2][3] = fmaf(a2,w3,acc[2][3]);
            acc[3][0] = fmaf(a3,w0,acc[3][0]); acc[3][1] = fmaf(a3,w1,acc[3][1]);
            acc[3][2] = fmaf(a3,w2,acc[3][2]); acc[3][3] = fmaf(a3,w3,acc[3][3]);
        }
    }
}

__global__ void __launch_bounds__(NTHR, 1) lstm_kernel(
    const float* __restrict__ h_n,   const int* __restrict__ expanded,
    const int* __restrict__ tfmask,  const float* __restrict__ dropm,
    const float* __restrict__ embW,
    const float* __restrict__ Wih1,  const float* __restrict__ Whh1,
    const float* __restrict__ bih1,  const float* __restrict__ bhh1,
    const float* __restrict__ Wih2,  const float* __restrict__ Whh2,
    const float* __restrict__ bih2,  const float* __restrict__ bhh2,
    const float* __restrict__ Wout,  const float* __restrict__ bout,
    float* __restrict__ out)
{
    __shared__ float sA[128][17];
    __shared__ float sW[32][17];
    __shared__ float s_rv[NTHR];
    __shared__ int   s_ri[NTHR];
    __shared__ int   s_tok;
    __shared__ float s_sc;

    const int tid = threadIdx.x;
    const int blk = blockIdx.x;
    const int rg  = tid >> 3;
    const int jj  = tid & 7;

    // ---------------- init: zero states, build x0, precompute hn const ------
    for (int i = blk * NTHR + tid; i < BATCH * HID; i += NBLK * NTHR) {
        g_h1[0][i] = 0.f; g_h2[0][i] = 0.f;
    }
    for (int i = blk * NTHR + tid; i < BATCH * EMB; i += NBLK * NTHR) {
        int b = i / EMB; int e = i - b * EMB;
        int tok = expanded[b * SEQT];
        g_x[i] = dropm[tok] * embW[(size_t)tok * EMB + e];
    }
    {   // g_hn tile: plain GEMM 128 x 4096, one 32-col tile per block
        int n0 = blk * 32;
        float acc[4][4];
        #pragma unroll
        for (int g = 0; g < 4; g++) {
            int col = n0 + g * 8 + jj;
            float bi = bih1[col] + bhh1[col];
            #pragma unroll
            for (int i2 = 0; i2 < 4; i2++) acc[i2][g] = bi;
        }
        mm_accum<false>(acc, h_n, CTXW, CTXW, Wih1, EMB + CTXW, EMB, n0, G4H - 1, sA, sW);
        #pragma unroll
        for (int i2 = 0; i2 < 4; i2++) {
            int r = rg * 4 + i2;
            #pragma unroll
            for (int g = 0; g < 4; g++)
                g_hn[(size_t)r * G4H + n0 + g * 8 + jj] = acc[i2][g];
        }
    }
    gbar();

    float c1r[4] = {0.f, 0.f, 0.f, 0.f};
    float c2r[4] = {0.f, 0.f, 0.f, 0.f};
    const int j0 = blk * 8;   // this block owns j columns [j0, j0+8) of both layers

    for (int t = 0; t < STEPS; t++) {
        const float* h1o = g_h1[t & 1];
        float*       h1n = g_h1[(t + 1) & 1];
        const float* h2o = g_h2[t & 1];
        float*       h2n = g_h2[(t + 1) & 1];

        // -------- phase A: layer-1 gates + cell (fused) --------
        {
            float acc[4][4];
            #pragma unroll
            for (int i2 = 0; i2 < 4; i2++) {
                int r = rg * 4 + i2;
                #pragma unroll
                for (int g = 0; g < 4; g++)
                    acc[i2][g] = g_hn[(size_t)r * G4H + g * HID + j0 + jj];
            }
            mm_accum<true>(acc, g_x, EMB, EMB, Wih1, EMB + CTXW, 0, j0, 0, sA, sW);
            mm_accum<true>(acc, h1o, HID, HID, Whh1, HID, 0, j0, 0, sA, sW);
            #pragma unroll
            for (int i2 = 0; i2 < 4; i2++) {
                int r = rg * 4 + i2;
                float ig = sigmf(acc[i2][0]);
                float fg = sigmf(acc[i2][1]);
                float gg = tanhf(acc[i2][2]);
                float og = sigmf(acc[i2][3]);
                float cn = fg * c1r[i2] + ig * gg;
                c1r[i2] = cn;
                h1n[r * HID + j0 + jj] = og * tanhf(cn);
            }
        }
        gbar();

        // -------- phase B: layer-2 gates + cell (fused) --------
        {
            float acc[4][4];
            #pragma unroll
            for (int g = 0; g < 4; g++) {
                int col = g * HID + j0 + jj;
                float bi = bih2[col] + bhh2[col];
                #pragma unroll
                for (int i2 = 0; i2 < 4; i2++) acc[i2][g] = bi;
            }
            mm_accum<true>(acc, h1n, HID, HID, Wih2, HID, 0, j0, 0, sA, sW);
            mm_accum<true>(acc, h2o, HID, HID, Whh2, HID, 0, j0, 0, sA, sW);
            #pragma unroll
            for (int i2 = 0; i2 < 4; i2++) {
                int r = rg * 4 + i2;
                float ig = sigmf(acc[i2][0]);
                float fg = sigmf(acc[i2][1]);
                float gg = tanhf(acc[i2][2]);
                float og = sigmf(acc[i2][3]);
                float cn = fg * c2r[i2] + ig * gg;
                c2r[i2] = cn;
                h2n[r * HID + j0 + jj] = og * tanhf(cn);
            }
        }
        gbar();

        // -------- phase C: logits GEMM + per-tile row-max partials --------
        for (int tile = blk; tile < NTILE_OUT; tile += NBLK) {
            int n0 = tile * 32;
            float acc[4][4];
            #pragma unroll
            for (int g = 0; g < 4; g++) {
                int col = n0 + g * 8 + jj;
                float bi = (col < VOC) ? bout[col] : -FLT_MAX;
                #pragma unroll
                for (int i2 = 0; i2 < 4; i2++) acc[i2][g] = bi;
            }
            mm_accum<false>(acc, h2n, HID, HID, Wout, HID, 0, n0, VOC - 1, sA, sW);
            #pragma unroll
            for (int i2 = 0; i2 < 4; i2++) {
                int r = rg * 4 + i2;
                float bv = -FLT_MAX; int bc = 0x7fffffff;
                size_t ob = ((size_t)t * BATCH + r) * VOC;
                #pragma unroll
                for (int g = 0; g < 4; g++) {
                    int col = n0 + g * 8 + jj;
                    if (col < VOC) {
                        out[ob + col] = acc[i2][g];
                        if (acc[i2][g] > bv) { bv = acc[i2][g]; bc = col; }
                    }
                }
                #pragma unroll
                for (int d = 4; d > 0; d >>= 1) {
                    float ov = __shfl_down_sync(0xffffffffu, bv, d, 8);
                    int   oc = __shfl_down_sync(0xffffffffu, bc, d, 8);
                    if (ov > bv || (ov == bv && oc < bc)) { bv = ov; bc = oc; }
                }
                if (jj == 0) { g_pmax[r][tile] = bv; g_pidx[r][tile] = bc; }
            }
        }
        gbar();

        // -------- phase D: final argmax per row + next-input select --------
        {
            int b = blk;
            float bv = -FLT_MAX; int bc = 0x7fffffff;
            for (int tile = tid; tile < NTILE_OUT; tile += NTHR) {
                float v = __ldcg(&g_pmax[b][tile]);
                int   c = __ldcg(&g_pidx[b][tile]);
                if (v > bv || (v == bv && c < bc)) { bv = v; bc = c; }
            }
            s_rv[tid] = bv; s_ri[tid] = bc;
            __syncthreads();
            for (int s = NTHR / 2; s > 0; s >>= 1) {
                if (tid < s) {
                    float v = s_rv[tid + s]; int c = s_ri[tid + s];
                    if (v > s_rv[tid] || (v == s_rv[tid] && c < s_ri[tid])) {
                        s_rv[tid] = v; s_ri[tid] = c;
                    }
                }
                __syncthreads();
            }
            if (tid == 0) {
                int m = tfmask[t * BATCH + b];
                int tok; float sc;
                if (m == 1) { tok = s_ri[0]; sc = 1.0f; }
                else        { tok = expanded[b * SEQT + t + 1]; sc = dropm[tok]; }
                s_tok = tok; s_sc = sc;
            }
            __syncthreads();
            int tok = s_tok; float sc = s_sc;
            for (int e = tid; e < EMB; e += NTHR)
                g_x[b * EMB + e] = sc * embW[(size_t)tok * EMB + e];
        }
        gbar();
    }
}

extern "C" void kernel_launch(void* const* d_in, const int* in_sizes, int n_in,
                              void* d_out, int out_size) {
    (void)in_sizes; (void)n_in; (void)out_size;
    lstm_kernel<<<NBLK, NTHR>>>(
        (const float*)d_in[0],  (const int*)d_in[1],  (const int*)d_in[2],
        (const float*)d_in[3],  (const float*)d_in[4], (const float*)d_in[5],
        (const float*)d_in[6],  (const float*)d_in[7], (const float*)d_in[8],
        (const float*)d_in[9],  (const float*)d_in[10], (const float*)d_in[11],
        (const float*)d_in[12], (const float*)d_in[13], (const float*)d_in[14],
        (float*)d_out);
}